// round 10
// baseline (speedup 1.0000x reference)
#include <cuda_runtime.h>
#include <cstdint>

#define WG_EPS 1e-8f
#define MT 32                 // Gaussians per warp-microtile
#define THREADS 256
#define WARPS (THREADS / 32)
#define STAGES 2

// Per-warp stage: 32 Gaussians x 30 floats = 3840 B
struct __align__(16) WStage {
    float l1[3 * MT];   // 24 float4
    float s1[3 * MT];
    float l2[3 * MT];
    float s2[3 * MT];
    float r1[9 * MT];   // 72 float4
    float r2[9 * MT];
};
// smem total = WARPS * STAGES * 3840 = 61440 B -> 3 CTAs/SM

__device__ __forceinline__ uint32_t smem_u32(const void* p) {
    return (uint32_t)__cvta_generic_to_shared(p);
}
__device__ __forceinline__ void cp16(void* dst_smem, const void* src) {
    asm volatile("cp.async.cg.shared.global [%0], [%1], 16;"
                 :: "r"(smem_u32(dst_smem)), "l"(src) : "memory");
}
__device__ __forceinline__ void cp_commit() {
    asm volatile("cp.async.commit_group;" ::: "memory");
}
template <int N>
__device__ __forceinline__ void cp_wait() {
    asm volatile("cp.async.wait_group %0;" :: "n"(N) : "memory");
}

__device__ __forceinline__ void fill_wstage(
    WStage* st, int t, int lane,
    const float* loc1, const float* scale1, const float* rot1,
    const float* loc2, const float* scale2, const float* rot2)
{
    const float4* pl1 = (const float4*)(loc1   + 3 * MT * t);
    const float4* ps1 = (const float4*)(scale1 + 3 * MT * t);
    const float4* pl2 = (const float4*)(loc2   + 3 * MT * t);
    const float4* ps2 = (const float4*)(scale2 + 3 * MT * t);
    const float4* pr1 = (const float4*)(rot1   + 9 * MT * t);
    const float4* pr2 = (const float4*)(rot2   + 9 * MT * t);

    if (lane < 24) {   // 3*MT/4 = 24 float4 per small array
        cp16((float4*)st->l1 + lane, pl1 + lane);
        cp16((float4*)st->s1 + lane, ps1 + lane);
        cp16((float4*)st->l2 + lane, pl2 + lane);
        cp16((float4*)st->s2 + lane, ps2 + lane);
    }
    // 9*MT/4 = 72 float4 per rot array
    cp16((float4*)st->r1 + lane,      pr1 + lane);
    cp16((float4*)st->r1 + lane + 32, pr1 + lane + 32);
    cp16((float4*)st->r2 + lane,      pr2 + lane);
    cp16((float4*)st->r2 + lane + 32, pr2 + lane + 32);
    if (lane < 8) {
        cp16((float4*)st->r1 + lane + 64, pr1 + lane + 64);
        cp16((float4*)st->r2 + lane + 64, pr2 + lane + 64);
    }
}

__device__ __forceinline__ float wg_compute(
    const float l1[3], const float s1[3], const float r1[9],
    const float l2[3], const float s2[3], const float r2[9])
{
    float d0 = l1[0] - l2[0], d1 = l1[1] - l2[1], d2 = l1[2] - l2[2];
    float loc_diff2 = d0 * d0 + d1 * d1 + d2 * d2;

    float cov2[3][3];
#pragma unroll
    for (int i = 0; i < 3; i++) {
#pragma unroll
        for (int k = i; k < 3; k++) {
            float v = r2[3 * i + 0] * s2[0] * r2[3 * k + 0]
                    + r2[3 * i + 1] * s2[1] * r2[3 * k + 1]
                    + r2[3 * i + 2] * s2[2] * r2[3 * k + 2];
            cov2[i][k] = v;
            cov2[k][i] = v;
        }
    }
    float tr_cov2 = cov2[0][0] + cov2[1][1] + cov2[2][2];

    float T[3][3];
#pragma unroll
    for (int j = 0; j < 3; j++)
#pragma unroll
        for (int l = 0; l < 3; l++)
            T[j][l] = cov2[j][0] * r1[0 * 3 + l]
                    + cov2[j][1] * r1[1 * 3 + l]
                    + cov2[j][2] * r1[2 * 3 + l];

    float M[3][3];
#pragma unroll
    for (int i = 0; i < 3; i++)
#pragma unroll
        for (int l = 0; l < 3; l++)
            M[i][l] = r1[0 * 3 + i] * T[0][l]
                    + r1[1 * 3 + i] * T[1][l]
                    + r1[2 * 3 + i] * T[2][l];

    float q0 = sqrtf(s1[0]), q1 = sqrtf(s1[1]), q2 = sqrtf(s1[2]);
    float a00 = s1[0] * M[0][0] + WG_EPS;
    float a11 = s1[1] * M[1][1] + WG_EPS;
    float a22 = s1[2] * M[2][2] + WG_EPS;
    float a01 = q0 * q1 * 0.5f * (M[0][1] + M[1][0]);
    float a02 = q0 * q2 * 0.5f * (M[0][2] + M[2][0]);
    float a12 = q1 * q2 * 0.5f * (M[1][2] + M[2][1]);

    float q  = (a00 + a11 + a22) * (1.0f / 3.0f);
    float p1 = a01 * a01 + a02 * a02 + a12 * a12;
    float m0 = a00 - q, m1 = a11 - q, m2 = a22 - q;
    float p2 = m0 * m0 + m1 * m1 + m2 * m2 + 2.0f * p1;

    float sum_sqrt;
    if (p2 <= 1e-24f) {
        sum_sqrt = 3.0f * sqrtf(fmaxf(q, WG_EPS));
    } else {
        float p  = sqrtf(p2 * (1.0f / 6.0f));
        float ip = 1.0f / p;
        float b00 = m0 * ip, b11 = m1 * ip, b22 = m2 * ip;
        float b01 = a01 * ip, b02 = a02 * ip, b12 = a12 * ip;
        float detB = b00 * (b11 * b22 - b12 * b12)
                   - b01 * (b01 * b22 - b12 * b02)
                   + b02 * (b01 * b12 - b11 * b02);
        float r = fminf(fmaxf(0.5f * detB, -1.0f), 1.0f);
        float phi = acosf(r) * (1.0f / 3.0f);
        float tp = 2.0f * p;
        float e1 = q + tp * cosf(phi);
        float e3 = q + tp * cosf(phi + 2.0943951023931953f);
        float e2 = 3.0f * q - e1 - e3;
        sum_sqrt = sqrtf(fmaxf(e1, WG_EPS))
                 + sqrtf(fmaxf(e2, WG_EPS))
                 + sqrtf(fmaxf(e3, WG_EPS));
    }

    float cov_w = (s1[0] + s1[1] + s1[2]) + tr_cov2 - 2.0f * sum_sqrt;
    cov_w = fmaxf(cov_w, 0.0f);
    return sqrtf(fmaxf(loc_diff2 + cov_w, WG_EPS));
}

__global__ __launch_bounds__(THREADS) void wasserstein_gaussian_kernel(
    const float* __restrict__ loc1,
    const float* __restrict__ scale1,
    const float* __restrict__ rot1,
    const float* __restrict__ loc2,
    const float* __restrict__ scale2,
    const float* __restrict__ rot2,
    float* __restrict__ out,
    int B, int nmt)
{
    extern __shared__ __align__(16) char smem_raw[];
    const int lane = threadIdx.x & 31;
    const int w    = threadIdx.x >> 5;
    WStage* my = (WStage*)smem_raw + w * STAGES;   // this warp's STAGES stages

    const int gw     = blockIdx.x * WARPS + w;     // global warp id
    const int stride = gridDim.x * WARPS;

    // ---- prologue: fill this warp's stages ----
#pragma unroll
    for (int k = 0; k < STAGES; k++) {
        int t = gw + k * stride;
        if (t < nmt)
            fill_wstage(&my[k], t, lane, loc1, scale1, rot1, loc2, scale2, rot2);
        cp_commit();   // uniform per warp: keep per-thread group counts aligned
    }

    // ---- per-warp independent pipeline (no block barriers) ----
    int i = 0;
    for (int t = gw; t < nmt; t += stride, i++) {
        int s = i & (STAGES - 1);
        cp_wait<STAGES - 1>();   // this thread's stage-s copies have landed
        __syncwarp();            // ...and every lane's copies in this warp

        WStage* st = &my[s];
        float l1v[3], l2v[3], s1v[3], s2v[3], r1v[9], r2v[9];
#pragma unroll
        for (int k = 0; k < 3; k++) {
            l1v[k] = st->l1[3 * lane + k];
            l2v[k] = st->l2[3 * lane + k];
            s1v[k] = fmaxf(st->s1[3 * lane + k], WG_EPS);
            s2v[k] = fmaxf(st->s2[3 * lane + k], WG_EPS);
        }
#pragma unroll
        for (int k = 0; k < 9; k++) {
            r1v[k] = st->r1[9 * lane + k];   // stride 9: bank-conflict-free
            r2v[k] = st->r2[9 * lane + k];
        }

        out[t * MT + lane] = wg_compute(l1v, s1v, r1v, l2v, s2v, r2v);

        __syncwarp();            // all lanes done reading stage s before refill

        int tn = t + STAGES * stride;
        if (tn < nmt)
            fill_wstage(st, tn, lane, loc1, scale1, rot1, loc2, scale2, rot2);
        cp_commit();
    }

    // ---- tail (B % MT != 0): CTA 0 direct loads ----
    if (blockIdx.x == 0) {
        for (int b = nmt * MT + threadIdx.x; b < B; b += THREADS) {
            float l1v[3], l2v[3], s1v[3], s2v[3], r1v[9], r2v[9];
#pragma unroll
            for (int k = 0; k < 3; k++) {
                l1v[k] = loc1[3 * b + k];
                l2v[k] = loc2[3 * b + k];
                s1v[k] = fmaxf(scale1[3 * b + k], WG_EPS);
                s2v[k] = fmaxf(scale2[3 * b + k], WG_EPS);
            }
#pragma unroll
            for (int k = 0; k < 9; k++) {
                r1v[k] = rot1[9 * b + k];
                r2v[k] = rot2[9 * b + k];
            }
            out[b] = wg_compute(l1v, s1v, r1v, l2v, s2v, r2v);
        }
    }
}

extern "C" void kernel_launch(void* const* d_in, const int* in_sizes, int n_in,
                              void* d_out, int out_size)
{
    const float* loc1   = (const float*)d_in[0];
    const float* scale1 = (const float*)d_in[1];
    const float* rot1   = (const float*)d_in[2];
    const float* loc2   = (const float*)d_in[3];
    const float* scale2 = (const float*)d_in[4];
    const float* rot2   = (const float*)d_in[5];
    float* out = (float*)d_out;

    int B = in_sizes[0] / 3;
    int nmt = B / MT;   // full 32-Gaussian microtiles

    int smem_bytes = WARPS * STAGES * (int)sizeof(WStage);  // 61440
    cudaFuncSetAttribute(wasserstein_gaussian_kernel,
                         cudaFuncAttributeMaxDynamicSharedMemorySize, smem_bytes);

    int blocks = 148 * 3;   // persistent, 3 CTAs/SM
    wasserstein_gaussian_kernel<<<blocks, THREADS, smem_bytes>>>(
        loc1, scale1, rot1, loc2, scale2, rot2, out, B, nmt);
}

// round 12
// speedup vs baseline: 1.0168x; 1.0168x over previous
#include <cuda_runtime.h>
#include <cuda_bf16.h>

#define WG_EPS 1e-8f
#define BLK 256

// Volatile asm: each load pinned to its own destination register, ordered
// before all consumption. Combined with __launch_bounds__(BLK, 4) (64-reg
// budget) this keeps ~30 LDGs in flight per thread.
__device__ __forceinline__ float ldg_nc(const float* p) {
    float v;
    asm volatile("ld.global.nc.f32 %0, [%1];" : "=f"(v) : "l"(p));
    return v;
}

__global__ __launch_bounds__(BLK, 4) void wasserstein_gaussian_kernel(
    const float* __restrict__ loc1,
    const float* __restrict__ scale1,
    const float* __restrict__ rot1,
    const float* __restrict__ loc2,
    const float* __restrict__ scale2,
    const float* __restrict__ rot2,
    float* __restrict__ out,
    int B)
{
    int b = blockIdx.x * blockDim.x + threadIdx.x;
    if (b >= B) return;

    // ---- issue ALL 30 loads before any compute ----
    float r1[9], r2[9];
#pragma unroll
    for (int i = 0; i < 9; i++) r1[i] = ldg_nc(rot1 + 9 * b + i);
#pragma unroll
    for (int i = 0; i < 9; i++) r2[i] = ldg_nc(rot2 + 9 * b + i);

    float l1[3], l2[3], s1r[3], s2r[3];
#pragma unroll
    for (int i = 0; i < 3; i++) l1[i]  = ldg_nc(loc1 + 3 * b + i);
#pragma unroll
    for (int i = 0; i < 3; i++) l2[i]  = ldg_nc(loc2 + 3 * b + i);
#pragma unroll
    for (int i = 0; i < 3; i++) s1r[i] = ldg_nc(scale1 + 3 * b + i);
#pragma unroll
    for (int i = 0; i < 3; i++) s2r[i] = ldg_nc(scale2 + 3 * b + i);

    float s1[3], s2[3];
#pragma unroll
    for (int i = 0; i < 3; i++) {
        s1[i] = fmaxf(s1r[i], WG_EPS);
        s2[i] = fmaxf(s2r[i], WG_EPS);
    }

    // ---- loc term ----
    float d0 = l1[0] - l2[0], d1 = l1[1] - l2[1], d2 = l1[2] - l2[2];
    float loc_diff2 = d0 * d0 + d1 * d1 + d2 * d2;

    // ---- cov2 = R2 diag(s2) R2^T (6 unique entries) ----
    float cov2[3][3];
#pragma unroll
    for (int i = 0; i < 3; i++) {
#pragma unroll
        for (int k = i; k < 3; k++) {
            float v = r2[3 * i + 0] * s2[0] * r2[3 * k + 0]
                    + r2[3 * i + 1] * s2[1] * r2[3 * k + 1]
                    + r2[3 * i + 2] * s2[2] * r2[3 * k + 2];
            cov2[i][k] = v;
            cov2[k][i] = v;
        }
    }
    float tr_cov2 = cov2[0][0] + cov2[1][1] + cov2[2][2];

    // ---- M = R1^T cov2 R1 ----
    float T[3][3];
#pragma unroll
    for (int j = 0; j < 3; j++)
#pragma unroll
        for (int l = 0; l < 3; l++)
            T[j][l] = cov2[j][0] * r1[0 * 3 + l]
                    + cov2[j][1] * r1[1 * 3 + l]
                    + cov2[j][2] * r1[2 * 3 + l];

    float M[3][3];
#pragma unroll
    for (int i = 0; i < 3; i++)
#pragma unroll
        for (int l = 0; l < 3; l++)
            M[i][l] = r1[0 * 3 + i] * T[0][l]
                    + r1[1 * 3 + i] * T[1][l]
                    + r1[2 * 3 + i] * T[2][l];

    // ---- E = diag(sqrt(s1)) M diag(sqrt(s1)), symmetrized + EPS*I ----
    float q0 = sqrtf(s1[0]), q1 = sqrtf(s1[1]), q2 = sqrtf(s1[2]);
    float a00 = s1[0] * M[0][0] + WG_EPS;
    float a11 = s1[1] * M[1][1] + WG_EPS;
    float a22 = s1[2] * M[2][2] + WG_EPS;
    float a01 = q0 * q1 * 0.5f * (M[0][1] + M[1][0]);
    float a02 = q0 * q2 * 0.5f * (M[0][2] + M[2][0]);
    float a12 = q1 * q2 * 0.5f * (M[1][2] + M[2][1]);

    // ---- eigenvalues of symmetric 3x3 (trigonometric / Smith method) ----
    float q  = (a00 + a11 + a22) * (1.0f / 3.0f);
    float p1 = a01 * a01 + a02 * a02 + a12 * a12;
    float m0 = a00 - q, m1 = a11 - q, m2 = a22 - q;
    float p2 = m0 * m0 + m1 * m1 + m2 * m2 + 2.0f * p1;

    float sum_sqrt;
    if (p2 <= 1e-24f) {
        sum_sqrt = 3.0f * sqrtf(fmaxf(q, WG_EPS));
    } else {
        float p  = sqrtf(p2 * (1.0f / 6.0f));
        float ip = 1.0f / p;
        float b00 = m0 * ip, b11 = m1 * ip, b22 = m2 * ip;
        float b01 = a01 * ip, b02 = a02 * ip, b12 = a12 * ip;
        float detB = b00 * (b11 * b22 - b12 * b12)
                   - b01 * (b01 * b22 - b12 * b02)
                   + b02 * (b01 * b12 - b11 * b02);
        float r = fminf(fmaxf(0.5f * detB, -1.0f), 1.0f);
        float phi = acosf(r) * (1.0f / 3.0f);
        float tp = 2.0f * p;
        float e1 = q + tp * cosf(phi);                       // largest
        float e3 = q + tp * cosf(phi + 2.0943951023931953f); // smallest
        float e2 = 3.0f * q - e1 - e3;
        sum_sqrt = sqrtf(fmaxf(e1, WG_EPS))
                 + sqrtf(fmaxf(e2, WG_EPS))
                 + sqrtf(fmaxf(e3, WG_EPS));
    }

    // ---- assemble W2 ----
    float cov_w = (s1[0] + s1[1] + s1[2]) + tr_cov2 - 2.0f * sum_sqrt;
    cov_w = fmaxf(cov_w, 0.0f);
    out[b] = sqrtf(fmaxf(loc_diff2 + cov_w, WG_EPS));
}

extern "C" void kernel_launch(void* const* d_in, const int* in_sizes, int n_in,
                              void* d_out, int out_size)
{
    const float* loc1   = (const float*)d_in[0];
    const float* scale1 = (const float*)d_in[1];
    const float* rot1   = (const float*)d_in[2];
    const float* loc2   = (const float*)d_in[3];
    const float* scale2 = (const float*)d_in[4];
    const float* rot2   = (const float*)d_in[5];
    float* out = (float*)d_out;

    int B = in_sizes[0] / 3;
    int blocks = (B + BLK - 1) / BLK;
    wasserstein_gaussian_kernel<<<blocks, BLK>>>(
        loc1, scale1, rot1, loc2, scale2, rot2, out, B);
}

// round 13
// speedup vs baseline: 1.0816x; 1.0638x over previous
#include <cuda_runtime.h>
#include <cuda_bf16.h>

#define WG_EPS 1e-8f
#define BLK 256

__global__ __launch_bounds__(BLK) void wasserstein_gaussian_kernel(
    const float* __restrict__ loc1,
    const float* __restrict__ scale1,
    const float* __restrict__ rot1,
    const float* __restrict__ loc2,
    const float* __restrict__ scale2,
    const float* __restrict__ rot2,
    float* __restrict__ out,
    int B)
{
    int b = blockIdx.x * blockDim.x + threadIdx.x;
    if (b >= B) return;

    // ---- loads (R2 structure: proven fastest) ----
    float l1[3], l2[3], s1[3], s2[3], r1[9], r2[9];
#pragma unroll
    for (int i = 0; i < 3; i++) {
        l1[i] = loc1[3 * b + i];
        l2[i] = loc2[3 * b + i];
        s1[i] = fmaxf(scale1[3 * b + i], WG_EPS);
        s2[i] = fmaxf(scale2[3 * b + i], WG_EPS);
    }
#pragma unroll
    for (int i = 0; i < 9; i++) {
        r1[i] = rot1[9 * b + i];
        r2[i] = rot2[9 * b + i];
    }

    // ---- loc term ----
    float d0 = l1[0] - l2[0], d1 = l1[1] - l2[1], d2 = l1[2] - l2[2];
    float loc_diff2 = d0 * d0 + d1 * d1 + d2 * d2;

    // ---- cov2 = R2 diag(s2) R2^T (6 unique entries) ----
    float cov2[3][3];
#pragma unroll
    for (int i = 0; i < 3; i++) {
#pragma unroll
        for (int k = i; k < 3; k++) {
            float v = r2[3 * i + 0] * s2[0] * r2[3 * k + 0]
                    + r2[3 * i + 1] * s2[1] * r2[3 * k + 1]
                    + r2[3 * i + 2] * s2[2] * r2[3 * k + 2];
            cov2[i][k] = v;
            cov2[k][i] = v;
        }
    }
    float tr_cov2 = cov2[0][0] + cov2[1][1] + cov2[2][2];

    // ---- M = R1^T cov2 R1 ----
    float T[3][3];
#pragma unroll
    for (int j = 0; j < 3; j++)
#pragma unroll
        for (int l = 0; l < 3; l++)
            T[j][l] = cov2[j][0] * r1[0 * 3 + l]
                    + cov2[j][1] * r1[1 * 3 + l]
                    + cov2[j][2] * r1[2 * 3 + l];

    float M[3][3];
#pragma unroll
    for (int i = 0; i < 3; i++)
#pragma unroll
        for (int l = 0; l < 3; l++)
            M[i][l] = r1[0 * 3 + i] * T[0][l]
                    + r1[1 * 3 + i] * T[1][l]
                    + r1[2 * 3 + i] * T[2][l];

    // ---- E = diag(sqrt(s1)) M diag(sqrt(s1)), symmetrized + EPS*I ----
    float q0 = sqrtf(s1[0]), q1 = sqrtf(s1[1]), q2 = sqrtf(s1[2]);
    float a00 = s1[0] * M[0][0] + WG_EPS;
    float a11 = s1[1] * M[1][1] + WG_EPS;
    float a22 = s1[2] * M[2][2] + WG_EPS;
    float a01 = q0 * q1 * 0.5f * (M[0][1] + M[1][0]);
    float a02 = q0 * q2 * 0.5f * (M[0][2] + M[2][0]);
    float a12 = q1 * q2 * 0.5f * (M[1][2] + M[2][1]);

    // ---- s = tr(E^{1/2}) via invariants + Newton (no eigenvalues, no trig) ----
    // s = sum sqrt(lambda_i) is the largest root of
    //   f(s) = s^4 - 2*I1*s^2 - 8*sqrt(I3)*s + (I1^2 - 4*I2) = 0
    // Start from the upper bound s0 = sqrt(I1 + 2*sqrt(3*I2)) >= s*;
    // f is increasing & convex on [s*, inf) -> monotone Newton descent.
    float I1 = a00 + a11 + a22;
    float I2 = (a00 * a11 - a01 * a01)
             + (a00 * a22 - a02 * a02)
             + (a11 * a22 - a12 * a12);
    float I3 = a00 * (a11 * a22 - a12 * a12)
             - a01 * (a01 * a22 - a12 * a02)
             + a02 * (a01 * a12 - a11 * a02);
    I1 = fmaxf(I1, 3.0f * WG_EPS);
    I2 = fmaxf(I2, 0.0f);
    I3 = fmaxf(I3, 0.0f);

    float c8 = 8.0f * sqrtf(I3);
    float K  = I1 * I1 - 4.0f * I2;
    float s  = sqrtf(I1 + 2.0f * sqrtf(3.0f * I2));   // >= s*

#pragma unroll
    for (int it = 0; it < 5; it++) {
        float s2v = s * s;
        float f   = (s2v - 2.0f * I1) * s2v - c8 * s + K;
        float fp  = s * (4.0f * s2v - 4.0f * I1) - c8;
        s -= f / fmaxf(fp, 1e-20f);
    }
    float sum_sqrt = fmaxf(s, 0.0f);

    // ---- assemble W2 ----
    float cov_w = (s1[0] + s1[1] + s1[2]) + tr_cov2 - 2.0f * sum_sqrt;
    cov_w = fmaxf(cov_w, 0.0f);
    out[b] = sqrtf(fmaxf(loc_diff2 + cov_w, WG_EPS));
}

extern "C" void kernel_launch(void* const* d_in, const int* in_sizes, int n_in,
                              void* d_out, int out_size)
{
    const float* loc1   = (const float*)d_in[0];
    const float* scale1 = (const float*)d_in[1];
    const float* rot1   = (const float*)d_in[2];
    const float* loc2   = (const float*)d_in[3];
    const float* scale2 = (const float*)d_in[4];
    const float* rot2   = (const float*)d_in[5];
    float* out = (float*)d_out;

    int B = in_sizes[0] / 3;
    int blocks = (B + BLK - 1) / BLK;
    wasserstein_gaussian_kernel<<<blocks, BLK>>>(
        loc1, scale1, rot1, loc2, scale2, rot2, out, B);
}